// round 15
// baseline (speedup 1.0000x reference)
#include <cuda_runtime.h>
#include <cuda_fp16.h>
#include <math.h>
#include <cstdint>

#define NN 100000
#define HID 128
#define NE 1600000
#define NC 10
#define NCHUNK 8
#define CH_TILES 196                       // tiles per chunk (last = 1563-7*196 = 191)
#define CH_NODES (CH_TILES * 64)           // 12544

// ---------------- scratch (device globals; no allocation allowed) -------------
__device__ int    g_cnt[NN];
__device__ int    g_rowptr[NN];
__device__ int    g_col[NE];
__device__ int    g_pos[NE];                   // intra-segment position per edge
__device__ int    g_blockSums[256];
__device__ __half g_bufH1[(size_t)NN * HID];   // layer-1 h' = invs*h (fp16)
__device__ __half g_bufH2[(size_t)NN * HID];   // layer-2 h' (fp16)
__device__ __half g_bufX[(size_t)NN * HID];    // layer-1 activation x (fp16)
// fp16 weight images, layout [n][k/2] u32 pairs
__device__ uint32_t g_W1i[128 * 64];
__device__ uint32_t g_W2i[128 * 64];

__device__ __forceinline__ uint32_t smem_u32(const void* p) {
    uint32_t a;
    asm("{ .reg .u64 t; cvta.to.shared.u64 t, %1; cvt.u32.u64 %0, t; }" : "=r"(a) : "l"(p));
    return a;
}

// ---------------- degree histogram + position record (single atomic pass) ----
__global__ void k_count(const int* __restrict__ dst) {
    int e4 = blockIdx.x * blockDim.x + threadIdx.x;
    if (e4 < NE / 4) {
        int4 d = ((const int4*)dst)[e4];
        int4 p;
        p.x = atomicAdd(&g_cnt[d.x], 1);
        p.y = atomicAdd(&g_cnt[d.y], 1);
        p.z = atomicAdd(&g_cnt[d.z], 1);
        p.w = atomicAdd(&g_cnt[d.w], 1);
        ((int4*)g_pos)[e4] = p;
    }
}

// ---------------- exclusive scan (3-phase) ----------------
__global__ void k_scanA() {
    __shared__ int s[512];
    int i = blockIdx.x * 512 + threadIdx.x;
    int v = (i < NN) ? g_cnt[i] : 0;
    s[threadIdx.x] = v;
    __syncthreads();
    #pragma unroll
    for (int off = 1; off < 512; off <<= 1) {
        int t = (threadIdx.x >= off) ? s[threadIdx.x - off] : 0;
        __syncthreads();
        s[threadIdx.x] += t;
        __syncthreads();
    }
    if (i < NN) g_rowptr[i] = s[threadIdx.x] - v;        // exclusive
    if (threadIdx.x == 511) g_blockSums[blockIdx.x] = s[511];
}

__global__ void k_scanB(int nblocks) {
    __shared__ int s[256];
    int t = threadIdx.x;
    int v = (t < nblocks) ? g_blockSums[t] : 0;
    s[t] = v;
    __syncthreads();
    #pragma unroll
    for (int off = 1; off < 256; off <<= 1) {
        int u = (t >= off) ? s[t - off] : 0;
        __syncthreads();
        s[t] += u;
        __syncthreads();
    }
    if (t < nblocks) g_blockSums[t] = s[t] - v;           // exclusive
}

__global__ void k_scanC() {
    int i = blockIdx.x * 512 + threadIdx.x;
    if (i < NN) g_rowptr[i] += g_blockSums[blockIdx.x];
}

// ---------------- CSR place (no atomics) ----------------
__global__ void k_place(const int* __restrict__ src, const int* __restrict__ dst) {
    int e4 = blockIdx.x * blockDim.x + threadIdx.x;
    if (e4 < NE / 4) {
        int4 s = ((const int4*)src)[e4];
        int4 d = ((const int4*)dst)[e4];
        int4 p = ((const int4*)g_pos)[e4];
        g_col[g_rowptr[d.x] + p.x] = s.x;
        g_col[g_rowptr[d.y] + p.y] = s.y;
        g_col[g_rowptr[d.z] + p.z] = s.z;
        g_col[g_rowptr[d.w] + p.w] = s.w;
    }
}

// ---------------- weight image precompute (single fp16) ----------------
__global__ void k_wimg(const float* __restrict__ W, int layer) {
    uint32_t* img = (layer == 0 ? g_W1i : g_W2i);
    int idx = blockIdx.x * blockDim.x + threadIdx.x;      // 0..8191 (pairs)
    if (idx >= 128 * 64) return;
    int n = idx >> 6, cp = idx & 63;
    int k0 = 2 * cp;
    float w0 = W[(size_t)k0 * HID + n];
    float w1 = W[(size_t)(k0 + 1) * HID + n];
    __half h0 = __float2half_rn(w0), h1 = __float2half_rn(w1);
    img[idx] = (uint32_t)__half_as_ushort(h0) | ((uint32_t)__half_as_ushort(h1) << 16);
}

// ---------------- single-pass fp16 GEMM, M-tile 64, 3 CTAs/SM ----------------
#define ROWW 68
#define MAT_A (64 * ROWW)
#define MAT_W (128 * ROWW)
#define DSMEM_SZ ((MAT_A + MAT_W) * 4)     // 52224 bytes

__device__ __forceinline__ void mma_f16(float* d, uint32_t a0, uint32_t a1,
                                        uint32_t a2, uint32_t a3,
                                        uint32_t b0, uint32_t b1) {
    asm volatile(
        "mma.sync.aligned.m16n8k16.row.col.f32.f16.f16.f32 "
        "{%0,%1,%2,%3}, {%4,%5,%6,%7}, {%8,%9}, {%0,%1,%2,%3};\n"
        : "+f"(d[0]), "+f"(d[1]), "+f"(d[2]), "+f"(d[3])
        : "r"(a0), "r"(a1), "r"(a2), "r"(a3), "r"(b0), "r"(b1));
}

__device__ __forceinline__ void ldsm_x4(uint32_t& r0, uint32_t& r1, uint32_t& r2,
                                        uint32_t& r3, uint32_t addr) {
    asm volatile("ldmatrix.sync.aligned.m8n8.x4.shared.b16 {%0,%1,%2,%3}, [%4];"
                 : "=r"(r0), "=r"(r1), "=r"(r2), "=r"(r3) : "r"(addr));
}

__global__ void __launch_bounds__(256, 3) k_gemm(const float* Af32, int layer, int tileBase) {
    extern __shared__ uint32_t sm[];
    uint32_t* sA = sm;
    uint32_t* sW = sm + MAT_A;

    const uint32_t* wImg = (layer == 0 ? g_W1i : g_W2i);
    __half* outH = (layer == 0 ? g_bufH1 : g_bufH2);

    int tid = threadIdx.x;
    int wid = tid >> 5, lane = tid & 31;
    int blockRow = (tileBase + blockIdx.x) * 64;

    // Stage W image
    #pragma unroll
    for (int i = 0; i < 32; i++) {
        int idx = tid + i * 256;
        int row = idx >> 6, c = idx & 63;
        sW[row * ROWW + c] = wImg[idx];
    }
    // A tile: layer 0 converts fp32 emb -> fp16; layer 1 raw-copies fp16 x
    #pragma unroll
    for (int i = 0; i < 16; i++) {
        int idx = tid + i * 256;
        int row = idx >> 6, c = idx & 63;
        int gr = blockRow + row;
        uint32_t u = 0;
        if (gr < NN) {
            if (Af32) {
                float2 v = *(const float2*)&Af32[(size_t)gr * HID + 2 * c];
                __half h0 = __float2half_rn(v.x), h1 = __float2half_rn(v.y);
                u = (uint32_t)__half_as_ushort(h0) | ((uint32_t)__half_as_ushort(h1) << 16);
            } else {
                u = ((const uint32_t*)(g_bufX + (size_t)gr * HID))[c];
            }
        }
        sA[row * ROWW + c] = u;
    }
    __syncthreads();

    float acc[8][4];
    #pragma unroll
    for (int j = 0; j < 8; j++)
        #pragma unroll
        for (int q = 0; q < 4; q++) acc[j][q] = 0.f;

    int rowGrp = wid & 3, nHalf = wid >> 2;
    int grp = lane >> 3, l8 = lane & 7;
    uint32_t base = smem_u32(sm);
    uint32_t aAddr = base + (uint32_t)((rowGrp * 16 + (grp & 1) * 8 + l8) * ROWW + (grp >> 1) * 4) * 4;
    uint32_t wAddr = base + MAT_A * 4 +
                     (uint32_t)((nHalf * 64 + (grp >> 1) * 8 + l8) * ROWW + (grp & 1) * 4) * 4;

    #pragma unroll
    for (int kc = 0; kc < 8; kc++) {
        uint32_t kB = kc * 32;
        uint32_t a0, a1, a2, a3;
        ldsm_x4(a0, a1, a2, a3, aAddr + kB);
        #pragma unroll
        for (int jp = 0; jp < 4; jp++) {
            uint32_t jB = (uint32_t)(jp * 16 * ROWW) * 4 + kB;
            uint32_t b0, b1, b2, b3;
            ldsm_x4(b0, b1, b2, b3, wAddr + jB);
            mma_f16(acc[2 * jp],     a0, a1, a2, a3, b0, b1);
            mma_f16(acc[2 * jp + 1], a0, a1, a2, a3, b2, b3);
        }
    }

    // Epilogue: scale by rsqrt(cnt+1), store fp16 h'
    int g = lane >> 2, t = lane & 3;
    int gr0 = blockRow + rowGrp * 16 + g;
    int gr1 = gr0 + 8;
    float wn0 = (gr0 < NN) ? rsqrtf((float)(g_cnt[gr0] + 1)) : 0.f;
    float wn1 = (gr1 < NN) ? rsqrtf((float)(g_cnt[gr1] + 1)) : 0.f;
    #pragma unroll
    for (int j = 0; j < 8; j++) {
        int col = nHalf * 64 + j * 8 + 2 * t;
        if (gr0 < NN)
            *(__half2*)&outH[(size_t)gr0 * HID + col] =
                __floats2half2_rn(wn0 * acc[j][0], wn0 * acc[j][1]);
        if (gr1 < NN)
            *(__half2*)&outH[(size_t)gr1 * HID + col] =
                __floats2half2_rn(wn1 * acc[j][2], wn1 * acc[j][3]);
    }
}

// ---------------- gather-aggregate + bias + relu (+ fused output proj) -------
// agg[n] = rsqrt(cnt[n]+1) * sum_{s in N(n) U {n}} h'[s];  x = relu(agg + b)
__global__ void k_agg(int layer, int nodeBase, const float* __restrict__ bias,
                      const float* __restrict__ Wout, const float* __restrict__ bout,
                      float* __restrict__ out) {
    const __half* h = (layer == 0 ? g_bufH1 : g_bufH2);
    __shared__ float Ws[HID * NC];
    __shared__ float bs[NC];

    int tid = threadIdx.x;
    if (Wout) {
        for (int i = tid; i < HID * NC; i += blockDim.x) Ws[i] = Wout[i];
        if (tid < NC) bs[tid] = bout[tid];
        __syncthreads();
    }

    int n = nodeBase + ((blockIdx.x * blockDim.x + tid) >> 5);   // grid sized exactly
    int lane = tid & 31;

    float ax, ay, az, aw;
    {
        uint2 v = ((const uint2*)(h + (size_t)n * HID))[lane];
        float2 p0 = __half22float2(*(const __half2*)&v.x);
        float2 p1 = __half22float2(*(const __half2*)&v.y);
        ax = p0.x; ay = p0.y; az = p1.x; aw = p1.y;   // self term h'[n]
    }

    int beg = g_rowptr[n];
    int cnt = g_cnt[n];
    int end = beg + cnt;

    int idx = beg;
    for (; idx + 3 < end; idx += 4) {                 // 4-way MLP
        int s0 = g_col[idx];
        int s1 = g_col[idx + 1];
        int s2 = g_col[idx + 2];
        int s3 = g_col[idx + 3];
        uint2 v0 = ((const uint2*)(h + (size_t)s0 * HID))[lane];
        uint2 v1 = ((const uint2*)(h + (size_t)s1 * HID))[lane];
        uint2 v2 = ((const uint2*)(h + (size_t)s2 * HID))[lane];
        uint2 v3 = ((const uint2*)(h + (size_t)s3 * HID))[lane];
        float2 a0 = __half22float2(*(const __half2*)&v0.x);
        float2 b0 = __half22float2(*(const __half2*)&v0.y);
        float2 a1 = __half22float2(*(const __half2*)&v1.x);
        float2 b1 = __half22float2(*(const __half2*)&v1.y);
        float2 a2 = __half22float2(*(const __half2*)&v2.x);
        float2 b2 = __half22float2(*(const __half2*)&v2.y);
        float2 a3 = __half22float2(*(const __half2*)&v3.x);
        float2 b3 = __half22float2(*(const __half2*)&v3.y);
        ax += (a0.x + a1.x) + (a2.x + a3.x);
        ay += (a0.y + a1.y) + (a2.y + a3.y);
        az += (b0.x + b1.x) + (b2.x + b3.x);
        aw += (b0.y + b1.y) + (b2.y + b3.y);
    }
    for (; idx < end; idx++) {
        int s0 = g_col[idx];
        uint2 v0 = ((const uint2*)(h + (size_t)s0 * HID))[lane];
        float2 a0 = __half22float2(*(const __half2*)&v0.x);
        float2 b0 = __half22float2(*(const __half2*)&v0.y);
        ax += a0.x; ay += a0.y; az += b0.x; aw += b0.y;
    }

    float wn = rsqrtf((float)(cnt + 1));
    float4 bv = ((const float4*)bias)[lane];
    float4 r;
    r.x = fmaxf(wn * ax + bv.x, 0.f);
    r.y = fmaxf(wn * ay + bv.y, 0.f);
    r.z = fmaxf(wn * az + bv.z, 0.f);
    r.w = fmaxf(wn * aw + bv.w, 0.f);

    if (!Wout) {
        uint2 o;
        *(__half2*)&o.x = __floats2half2_rn(r.x, r.y);
        *(__half2*)&o.y = __floats2half2_rn(r.z, r.w);
        ((uint2*)(g_bufX + (size_t)n * HID))[lane] = o;
    } else {
        int kb = lane * 4;
        #pragma unroll
        for (int c = 0; c < NC; c++) {
            float s = r.x * Ws[(kb + 0) * NC + c]
                    + r.y * Ws[(kb + 1) * NC + c]
                    + r.z * Ws[(kb + 2) * NC + c]
                    + r.w * Ws[(kb + 3) * NC + c];
            #pragma unroll
            for (int off = 16; off; off >>= 1)
                s += __shfl_down_sync(0xffffffffu, s, off);
            if (lane == 0) out[(size_t)n * NC + c] = s + bs[c];
        }
    }
}

// ---------------- launch ----------------
extern "C" void kernel_launch(void* const* d_in, const int* in_sizes, int n_in,
                              void* d_out, int out_size) {
    const int*   src  = (const int*)d_in[0];          // edge_index[0]
    const int*   dst  = src + NE;                     // edge_index[1]
    const float* emb  = (const float*)d_in[1];
    const float* W1   = (const float*)d_in[2];
    const float* b1   = (const float*)d_in[3];
    const float* W2   = (const float*)d_in[4];
    const float* b2   = (const float*)d_in[5];
    const float* Wout = (const float*)d_in[6];
    const float* bout = (const float*)d_in[7];
    float* out = (float*)d_out;

    const int SCAN_BLKS  = (NN + 511) / 512;          // 196
    const int EDGE4_BLKS = (NE / 4 + 255) / 256;      // 1563
    const int GEMM_BLKS  = (NN + 63) / 64;            // 1563
    const int AGG_BLKS   = (NN * 32) / 256;           // 12500

    static cudaStream_t s2 = nullptr;
    static cudaEvent_t evF = nullptr, evI = nullptr, evJ = nullptr, evG = nullptr;
    static cudaEvent_t evC[NCHUNK];
    static void* cntAddr = nullptr;
    if (!s2) {
        cudaFuncSetAttribute(k_gemm, cudaFuncAttributeMaxDynamicSharedMemorySize, DSMEM_SZ);
        cudaStreamCreateWithFlags(&s2, cudaStreamNonBlocking);
        cudaEventCreateWithFlags(&evF, cudaEventDisableTiming);
        cudaEventCreateWithFlags(&evI, cudaEventDisableTiming);
        cudaEventCreateWithFlags(&evJ, cudaEventDisableTiming);
        cudaEventCreateWithFlags(&evG, cudaEventDisableTiming);
        for (int c = 0; c < NCHUNK; c++)
            cudaEventCreateWithFlags(&evC[c], cudaEventDisableTiming);
        cudaGetSymbolAddress(&cntAddr, g_cnt);
    }

    // Fork: side stream starts weight images immediately (input-only deps)
    cudaEventRecord(evF, 0);
    cudaStreamWaitEvent(s2, evF, 0);
    k_wimg<<<32, 256, 0, s2>>>(W1, 0);
    k_wimg<<<32, 256, 0, s2>>>(W2, 1);

    // Main stream: counts (GEMM1's only prep dependency — epilogue rsqrt inline)
    cudaMemsetAsync(cntAddr, 0, NN * sizeof(int), 0);
    k_count<<<EDGE4_BLKS, 256>>>(dst);
    cudaEventRecord(evI, 0);

    // Side stream: GEMM1 overlaps remaining CSR build
    cudaStreamWaitEvent(s2, evI, 0);
    k_gemm<<<GEMM_BLKS, 256, DSMEM_SZ, s2>>>(emb, 0, 0);
    cudaEventRecord(evJ, s2);

    // Main stream: rest of CSR build
    k_scanA<<<SCAN_BLKS, 512>>>();
    k_scanB<<<1, 256>>>(SCAN_BLKS);
    k_scanC<<<SCAN_BLKS, 512>>>();
    k_place<<<EDGE4_BLKS, 256>>>(src, dst);

    // Join; then chunk-pipeline agg1 (main) with GEMM2 (side):
    // GEMM2 tile rows depend only on agg1 output for the SAME rows.
    cudaStreamWaitEvent(0, evJ, 0);
    for (int c = 0; c < NCHUNK; c++) {
        int nodeBase = c * CH_NODES;
        int nodes = (c == NCHUNK - 1) ? (NN - nodeBase) : CH_NODES;
        int aggBlks = nodes / 8;                       // nodes divisible by 8
        k_agg<<<aggBlks, 256>>>(0, nodeBase, b1, nullptr, nullptr, nullptr);
        cudaEventRecord(evC[c], 0);

        int tileBase = c * CH_TILES;
        int tiles = (c == NCHUNK - 1) ? (GEMM_BLKS - tileBase) : CH_TILES;
        cudaStreamWaitEvent(s2, evC[c], 0);
        k_gemm<<<tiles, 256, DSMEM_SZ, s2>>>(nullptr, 1, tileBase);
    }
    cudaEventRecord(evG, s2);

    // Final: layer-2 agg + fused output projection
    cudaStreamWaitEvent(0, evG, 0);
    k_agg<<<AGG_BLKS, 256>>>(1, 0, b2, Wout, bout, out);
}

// round 16
// speedup vs baseline: 1.1860x; 1.1860x over previous
#include <cuda_runtime.h>
#include <cuda_fp16.h>
#include <math.h>
#include <cstdint>

#define NN 100000
#define HID 128
#define NE 1600000
#define NC 10

// ---------------- scratch (device globals; no allocation allowed) -------------
__device__ int    g_cnt[NN];
__device__ int    g_rowptr[NN];
__device__ int    g_col[NE];
__device__ int    g_pos[NE];                   // intra-segment position per edge
__device__ int    g_blockSums[256];
__device__ __half g_bufH1[(size_t)NN * HID];   // layer-1 h' = invs*h (fp16)
__device__ __half g_bufH2[(size_t)NN * HID];   // layer-2 h' (fp16)
__device__ __half g_bufX[(size_t)NN * HID];    // layer-1 activation x (fp16)
// fp16 weight images, layout [n][k/2] u32 pairs
__device__ uint32_t g_W1i[128 * 64];
__device__ uint32_t g_W2i[128 * 64];

__device__ __forceinline__ uint32_t smem_u32(const void* p) {
    uint32_t a;
    asm("{ .reg .u64 t; cvta.to.shared.u64 t, %1; cvt.u32.u64 %0, t; }" : "=r"(a) : "l"(p));
    return a;
}

// ---------------- degree histogram + position record (single atomic pass) ----
__global__ void k_count(const int* __restrict__ dst) {
    int e4 = blockIdx.x * blockDim.x + threadIdx.x;
    if (e4 < NE / 4) {
        int4 d = ((const int4*)dst)[e4];
        int4 p;
        p.x = atomicAdd(&g_cnt[d.x], 1);
        p.y = atomicAdd(&g_cnt[d.y], 1);
        p.z = atomicAdd(&g_cnt[d.z], 1);
        p.w = atomicAdd(&g_cnt[d.w], 1);
        ((int4*)g_pos)[e4] = p;
    }
}

// ---------------- exclusive scan (3-phase) ----------------
__global__ void k_scanA() {
    __shared__ int s[512];
    int i = blockIdx.x * 512 + threadIdx.x;
    int v = (i < NN) ? g_cnt[i] : 0;
    s[threadIdx.x] = v;
    __syncthreads();
    #pragma unroll
    for (int off = 1; off < 512; off <<= 1) {
        int t = (threadIdx.x >= off) ? s[threadIdx.x - off] : 0;
        __syncthreads();
        s[threadIdx.x] += t;
        __syncthreads();
    }
    if (i < NN) g_rowptr[i] = s[threadIdx.x] - v;        // exclusive
    if (threadIdx.x == 511) g_blockSums[blockIdx.x] = s[511];
}

__global__ void k_scanB(int nblocks) {
    __shared__ int s[256];
    int t = threadIdx.x;
    int v = (t < nblocks) ? g_blockSums[t] : 0;
    s[t] = v;
    __syncthreads();
    #pragma unroll
    for (int off = 1; off < 256; off <<= 1) {
        int u = (t >= off) ? s[t - off] : 0;
        __syncthreads();
        s[t] += u;
        __syncthreads();
    }
    if (t < nblocks) g_blockSums[t] = s[t] - v;           // exclusive
}

__global__ void k_scanC() {
    int i = blockIdx.x * 512 + threadIdx.x;
    if (i < NN) g_rowptr[i] += g_blockSums[blockIdx.x];
}

// ---------------- CSR place (no atomics) ----------------
__global__ void k_place(const int* __restrict__ src, const int* __restrict__ dst) {
    int e4 = blockIdx.x * blockDim.x + threadIdx.x;
    if (e4 < NE / 4) {
        int4 s = ((const int4*)src)[e4];
        int4 d = ((const int4*)dst)[e4];
        int4 p = ((const int4*)g_pos)[e4];
        g_col[g_rowptr[d.x] + p.x] = s.x;
        g_col[g_rowptr[d.y] + p.y] = s.y;
        g_col[g_rowptr[d.z] + p.z] = s.z;
        g_col[g_rowptr[d.w] + p.w] = s.w;
    }
}

// ---------------- weight image precompute (single fp16) ----------------
__global__ void k_wimg(const float* __restrict__ W, int layer) {
    uint32_t* img = (layer == 0 ? g_W1i : g_W2i);
    int idx = blockIdx.x * blockDim.x + threadIdx.x;      // 0..8191 (pairs)
    if (idx >= 128 * 64) return;
    int n = idx >> 6, cp = idx & 63;
    int k0 = 2 * cp;
    float w0 = W[(size_t)k0 * HID + n];
    float w1 = W[(size_t)(k0 + 1) * HID + n];
    __half h0 = __float2half_rn(w0), h1 = __float2half_rn(w1);
    img[idx] = (uint32_t)__half_as_ushort(h0) | ((uint32_t)__half_as_ushort(h1) << 16);
}

// ---------------- single-pass fp16 GEMM, M-tile 64, 3 CTAs/SM ----------------
// h'[r][:] = rsqrt(cnt[r]+1) * (A[r][:] @ W), stored fp16.
#define ROWW 68
#define MAT_A (64 * ROWW)
#define MAT_W (128 * ROWW)
#define DSMEM_SZ ((MAT_A + MAT_W) * 4)     // 52224 bytes

__device__ __forceinline__ void mma_f16(float* d, uint32_t a0, uint32_t a1,
                                        uint32_t a2, uint32_t a3,
                                        uint32_t b0, uint32_t b1) {
    asm volatile(
        "mma.sync.aligned.m16n8k16.row.col.f32.f16.f16.f32 "
        "{%0,%1,%2,%3}, {%4,%5,%6,%7}, {%8,%9}, {%0,%1,%2,%3};\n"
        : "+f"(d[0]), "+f"(d[1]), "+f"(d[2]), "+f"(d[3])
        : "r"(a0), "r"(a1), "r"(a2), "r"(a3), "r"(b0), "r"(b1));
}

__device__ __forceinline__ void ldsm_x4(uint32_t& r0, uint32_t& r1, uint32_t& r2,
                                        uint32_t& r3, uint32_t addr) {
    asm volatile("ldmatrix.sync.aligned.m8n8.x4.shared.b16 {%0,%1,%2,%3}, [%4];"
                 : "=r"(r0), "=r"(r1), "=r"(r2), "=r"(r3) : "r"(addr));
}

__global__ void __launch_bounds__(256, 3) k_gemm(const float* Af32, int layer) {
    extern __shared__ uint32_t sm[];
    uint32_t* sA = sm;
    uint32_t* sW = sm + MAT_A;

    const uint32_t* wImg = (layer == 0 ? g_W1i : g_W2i);
    __half* outH = (layer == 0 ? g_bufH1 : g_bufH2);

    int tid = threadIdx.x;
    int wid = tid >> 5, lane = tid & 31;
    int blockRow = blockIdx.x * 64;

    // Stage W image (uint2-vectorized: 4096 uint2, 16 per thread)
    {
        const uint2* w2 = (const uint2*)wImg;
        #pragma unroll
        for (int i = 0; i < 16; i++) {
            int idx = tid + i * 256;              // 0..4095
            int row = idx >> 5, uc = idx & 31;    // 32 uint2 per row
            uint2 v = w2[idx];
            sW[row * ROWW + 2 * uc]     = v.x;
            sW[row * ROWW + 2 * uc + 1] = v.y;
        }
    }
    // A tile (vectorized): layer 0 fp32 emb via float4; layer 1 fp16 x via uint2
    if (Af32) {
        #pragma unroll
        for (int i = 0; i < 8; i++) {
            int idx = tid + i * 256;              // 0..2047 (float4 units)
            int row = idx >> 5, c4 = idx & 31;    // 32 float4 per row
            int gr = blockRow + row;
            float4 v = make_float4(0.f, 0.f, 0.f, 0.f);
            if (gr < NN) v = ((const float4*)(Af32 + (size_t)gr * HID))[c4];
            __half h0 = __float2half_rn(v.x), h1 = __float2half_rn(v.y);
            __half h2 = __float2half_rn(v.z), h3 = __float2half_rn(v.w);
            sA[row * ROWW + 2 * c4]     = (uint32_t)__half_as_ushort(h0) | ((uint32_t)__half_as_ushort(h1) << 16);
            sA[row * ROWW + 2 * c4 + 1] = (uint32_t)__half_as_ushort(h2) | ((uint32_t)__half_as_ushort(h3) << 16);
        }
    } else {
        #pragma unroll
        for (int i = 0; i < 8; i++) {
            int idx = tid + i * 256;              // 0..2047 (uint2 units)
            int row = idx >> 5, uc = idx & 31;
            int gr = blockRow + row;
            uint2 v = make_uint2(0u, 0u);
            if (gr < NN) v = ((const uint2*)(g_bufX + (size_t)gr * HID))[uc];
            sA[row * ROWW + 2 * uc]     = v.x;
            sA[row * ROWW + 2 * uc + 1] = v.y;
        }
    }
    __syncthreads();

    float acc[8][4];
    #pragma unroll
    for (int j = 0; j < 8; j++)
        #pragma unroll
        for (int q = 0; q < 4; q++) acc[j][q] = 0.f;

    int rowGrp = wid & 3, nHalf = wid >> 2;
    int grp = lane >> 3, l8 = lane & 7;
    uint32_t base = smem_u32(sm);
    uint32_t aAddr = base + (uint32_t)((rowGrp * 16 + (grp & 1) * 8 + l8) * ROWW + (grp >> 1) * 4) * 4;
    uint32_t wAddr = base + MAT_A * 4 +
                     (uint32_t)((nHalf * 64 + (grp >> 1) * 8 + l8) * ROWW + (grp & 1) * 4) * 4;

    #pragma unroll
    for (int kc = 0; kc < 8; kc++) {
        uint32_t kB = kc * 32;
        uint32_t a0, a1, a2, a3;
        ldsm_x4(a0, a1, a2, a3, aAddr + kB);
        #pragma unroll
        for (int jp = 0; jp < 4; jp++) {
            uint32_t jB = (uint32_t)(jp * 16 * ROWW) * 4 + kB;
            uint32_t b0, b1, b2, b3;
            ldsm_x4(b0, b1, b2, b3, wAddr + jB);
            mma_f16(acc[2 * jp],     a0, a1, a2, a3, b0, b1);
            mma_f16(acc[2 * jp + 1], a0, a1, a2, a3, b2, b3);
        }
    }

    // Epilogue: scale by rsqrt(cnt+1), store fp16 h'
    int g = lane >> 2, t = lane & 3;
    int gr0 = blockRow + rowGrp * 16 + g;
    int gr1 = gr0 + 8;
    float wn0 = (gr0 < NN) ? rsqrtf((float)(g_cnt[gr0] + 1)) : 0.f;
    float wn1 = (gr1 < NN) ? rsqrtf((float)(g_cnt[gr1] + 1)) : 0.f;
    #pragma unroll
    for (int j = 0; j < 8; j++) {
        int col = nHalf * 64 + j * 8 + 2 * t;
        if (gr0 < NN)
            *(__half2*)&outH[(size_t)gr0 * HID + col] =
                __floats2half2_rn(wn0 * acc[j][0], wn0 * acc[j][1]);
        if (gr1 < NN)
            *(__half2*)&outH[(size_t)gr1 * HID + col] =
                __floats2half2_rn(wn1 * acc[j][2], wn1 * acc[j][3]);
    }
}

// ---------------- gather-aggregate + bias + relu (+ fused output proj) -------
// agg[n] = rsqrt(cnt[n]+1) * sum_{s in N(n) U {n}} h'[s];  x = relu(agg + b)
__global__ void k_agg(int layer, const float* __restrict__ bias,
                      const float* __restrict__ Wout, const float* __restrict__ bout,
                      float* __restrict__ out) {
    const __half* h = (layer == 0 ? g_bufH1 : g_bufH2);
    __shared__ float Ws[HID * NC];
    __shared__ float bs[NC];

    int tid = threadIdx.x;
    if (Wout) {
        for (int i = tid; i < HID * NC; i += blockDim.x) Ws[i] = Wout[i];
        if (tid < NC) bs[tid] = bout[tid];
        __syncthreads();
    }

    int n = (blockIdx.x * blockDim.x + tid) >> 5;     // grid exact: 100000 warps
    int lane = tid & 31;

    float ax, ay, az, aw;
    {
        uint2 v = ((const uint2*)(h + (size_t)n * HID))[lane];
        float2 p0 = __half22float2(*(const __half2*)&v.x);
        float2 p1 = __half22float2(*(const __half2*)&v.y);
        ax = p0.x; ay = p0.y; az = p1.x; aw = p1.y;   // self term h'[n]
    }

    int beg = g_rowptr[n];
    int cnt = g_cnt[n];
    int end = beg + cnt;

    int idx = beg;
    for (; idx + 3 < end; idx += 4) {                 // 4-way MLP
        int s0 = g_col[idx];
        int s1 = g_col[idx + 1];
        int s2 = g_col[idx + 2];
        int s3 = g_col[idx + 3];
        uint2 v0 = ((const uint2*)(h + (size_t)s0 * HID))[lane];
        uint2 v1 = ((const uint2*)(h + (size_t)s1 * HID))[lane];
        uint2 v2 = ((const uint2*)(h + (size_t)s2 * HID))[lane];
        uint2 v3 = ((const uint2*)(h + (size_t)s3 * HID))[lane];
        float2 a0 = __half22float2(*(const __half2*)&v0.x);
        float2 b0 = __half22float2(*(const __half2*)&v0.y);
        float2 a1 = __half22float2(*(const __half2*)&v1.x);
        float2 b1 = __half22float2(*(const __half2*)&v1.y);
        float2 a2 = __half22float2(*(const __half2*)&v2.x);
        float2 b2 = __half22float2(*(const __half2*)&v2.y);
        float2 a3 = __half22float2(*(const __half2*)&v3.x);
        float2 b3 = __half22float2(*(const __half2*)&v3.y);
        ax += (a0.x + a1.x) + (a2.x + a3.x);
        ay += (a0.y + a1.y) + (a2.y + a3.y);
        az += (b0.x + b1.x) + (b2.x + b3.x);
        aw += (b0.y + b1.y) + (b2.y + b3.y);
    }
    for (; idx < end; idx++) {
        int s0 = g_col[idx];
        uint2 v0 = ((const uint2*)(h + (size_t)s0 * HID))[lane];
        float2 a0 = __half22float2(*(const __half2*)&v0.x);
        float2 b0 = __half22float2(*(const __half2*)&v0.y);
        ax += a0.x; ay += a0.y; az += b0.x; aw += b0.y;
    }

    float wn = rsqrtf((float)(cnt + 1));
    float4 bv = ((const float4*)bias)[lane];
    float4 r;
    r.x = fmaxf(wn * ax + bv.x, 0.f);
    r.y = fmaxf(wn * ay + bv.y, 0.f);
    r.z = fmaxf(wn * az + bv.z, 0.f);
    r.w = fmaxf(wn * aw + bv.w, 0.f);

    if (!Wout) {
        uint2 o;
        *(__half2*)&o.x = __floats2half2_rn(r.x, r.y);
        *(__half2*)&o.y = __floats2half2_rn(r.z, r.w);
        ((uint2*)(g_bufX + (size_t)n * HID))[lane] = o;
    } else {
        int kb = lane * 4;
        #pragma unroll
        for (int c = 0; c < NC; c++) {
            float s = r.x * Ws[(kb + 0) * NC + c]
                    + r.y * Ws[(kb + 1) * NC + c]
                    + r.z * Ws[(kb + 2) * NC + c]
                    + r.w * Ws[(kb + 3) * NC + c];
            #pragma unroll
            for (int off = 16; off; off >>= 1)
                s += __shfl_down_sync(0xffffffffu, s, off);
            if (lane == 0) out[(size_t)n * NC + c] = s + bs[c];
        }
    }
}

// ---------------- launch ----------------
extern "C" void kernel_launch(void* const* d_in, const int* in_sizes, int n_in,
                              void* d_out, int out_size) {
    const int*   src  = (const int*)d_in[0];          // edge_index[0]
    const int*   dst  = src + NE;                     // edge_index[1]
    const float* emb  = (const float*)d_in[1];
    const float* W1   = (const float*)d_in[2];
    const float* b1   = (const float*)d_in[3];
    const float* W2   = (const float*)d_in[4];
    const float* b2   = (const float*)d_in[5];
    const float* Wout = (const float*)d_in[6];
    const float* bout = (const float*)d_in[7];
    float* out = (float*)d_out;

    const int SCAN_BLKS  = (NN + 511) / 512;          // 196
    const int EDGE4_BLKS = (NE / 4 + 255) / 256;      // 1563
    const int GEMM_BLKS  = (NN + 63) / 64;            // 1563
    const int AGG_BLKS   = (NN * 32) / 256;           // 12500

    static cudaStream_t s2 = nullptr;
    static cudaEvent_t evF = nullptr, evI = nullptr, evJ = nullptr;
    static void* cntAddr = nullptr;
    if (!s2) {
        cudaFuncSetAttribute(k_gemm, cudaFuncAttributeMaxDynamicSharedMemorySize, DSMEM_SZ);
        cudaStreamCreateWithFlags(&s2, cudaStreamNonBlocking);
        cudaEventCreateWithFlags(&evF, cudaEventDisableTiming);
        cudaEventCreateWithFlags(&evI, cudaEventDisableTiming);
        cudaEventCreateWithFlags(&evJ, cudaEventDisableTiming);
        cudaGetSymbolAddress(&cntAddr, g_cnt);
    }

    // Fork: side stream starts weight images immediately (input-only deps)
    cudaEventRecord(evF, 0);
    cudaStreamWaitEvent(s2, evF, 0);
    k_wimg<<<32, 256, 0, s2>>>(W1, 0);
    k_wimg<<<32, 256, 0, s2>>>(W2, 1);

    // Main stream: counts (GEMM1's only prep dependency — epilogue rsqrt inline)
    cudaMemsetAsync(cntAddr, 0, NN * sizeof(int), 0);
    k_count<<<EDGE4_BLKS, 256>>>(dst);
    cudaEventRecord(evI, 0);

    // Side stream: GEMM1 overlaps remaining CSR build
    cudaStreamWaitEvent(s2, evI, 0);
    k_gemm<<<GEMM_BLKS, 256, DSMEM_SZ, s2>>>(emb, 0);
    cudaEventRecord(evJ, s2);

    // Main stream: rest of CSR build
    k_scanA<<<SCAN_BLKS, 512>>>();
    k_scanB<<<1, 256>>>(SCAN_BLKS);
    k_scanC<<<SCAN_BLKS, 512>>>();
    k_place<<<EDGE4_BLKS, 256>>>(src, dst);

    // Join, then layer-1 agg -> layer-2 GEMM -> layer-2 agg + output proj
    cudaStreamWaitEvent(0, evJ, 0);
    k_agg<<<AGG_BLKS, 256>>>(0, b1, nullptr, nullptr, nullptr);
    k_gemm<<<GEMM_BLKS, 256, DSMEM_SZ>>>(nullptr, 1);
    k_agg<<<AGG_BLKS, 256>>>(1, b2, Wout, bout, out);
}

// round 17
// speedup vs baseline: 1.1865x; 1.0005x over previous
#include <cuda_runtime.h>
#include <cuda_fp16.h>
#include <math.h>
#include <cstdint>

#define NN 100000
#define HID 128
#define NE 1600000
#define NC 10

// ---------------- scratch (device globals; no allocation allowed) -------------
__device__ int    g_cnt[NN];
__device__ int    g_rowptr[NN];
__device__ int    g_col[NE];
__device__ int    g_pos[NE];                   // intra-segment position per edge
__device__ int    g_blockSums[256];
__device__ __half g_bufH1[(size_t)NN * HID];   // layer-1 h' = invs*h (fp16)
__device__ __half g_bufH2[(size_t)NN * HID];   // layer-2 h' (fp16)
__device__ __half g_bufX[(size_t)NN * HID];    // layer-1 activation x (fp16)
// fp16 weight images, layout [n][k/2] u32 pairs
__device__ uint32_t g_W1i[128 * 64];
__device__ uint32_t g_W2i[128 * 64];

__device__ __forceinline__ uint32_t smem_u32(const void* p) {
    uint32_t a;
    asm("{ .reg .u64 t; cvta.to.shared.u64 t, %1; cvt.u32.u64 %0, t; }" : "=r"(a) : "l"(p));
    return a;
}

// ---------------- degree histogram + position record (single atomic pass) ----
__global__ void k_count(const int* __restrict__ dst) {
    int e4 = blockIdx.x * blockDim.x + threadIdx.x;
    if (e4 < NE / 4) {
        int4 d = ((const int4*)dst)[e4];
        int4 p;
        p.x = atomicAdd(&g_cnt[d.x], 1);
        p.y = atomicAdd(&g_cnt[d.y], 1);
        p.z = atomicAdd(&g_cnt[d.z], 1);
        p.w = atomicAdd(&g_cnt[d.w], 1);
        ((int4*)g_pos)[e4] = p;
    }
}

// ---------------- exclusive scan (3-phase) ----------------
__global__ void k_scanA() {
    __shared__ int s[512];
    int i = blockIdx.x * 512 + threadIdx.x;
    int v = (i < NN) ? g_cnt[i] : 0;
    s[threadIdx.x] = v;
    __syncthreads();
    #pragma unroll
    for (int off = 1; off < 512; off <<= 1) {
        int t = (threadIdx.x >= off) ? s[threadIdx.x - off] : 0;
        __syncthreads();
        s[threadIdx.x] += t;
        __syncthreads();
    }
    if (i < NN) g_rowptr[i] = s[threadIdx.x] - v;        // exclusive
    if (threadIdx.x == 511) g_blockSums[blockIdx.x] = s[511];
}

__global__ void k_scanB(int nblocks) {
    __shared__ int s[256];
    int t = threadIdx.x;
    int v = (t < nblocks) ? g_blockSums[t] : 0;
    s[t] = v;
    __syncthreads();
    #pragma unroll
    for (int off = 1; off < 256; off <<= 1) {
        int u = (t >= off) ? s[t - off] : 0;
        __syncthreads();
        s[t] += u;
        __syncthreads();
    }
    if (t < nblocks) g_blockSums[t] = s[t] - v;           // exclusive
}

__global__ void k_scanC() {
    int i = blockIdx.x * 512 + threadIdx.x;
    if (i < NN) g_rowptr[i] += g_blockSums[blockIdx.x];
}

// ---------------- CSR place (no atomics) ----------------
__global__ void k_place(const int* __restrict__ src, const int* __restrict__ dst) {
    int e4 = blockIdx.x * blockDim.x + threadIdx.x;
    if (e4 < NE / 4) {
        int4 s = ((const int4*)src)[e4];
        int4 d = ((const int4*)dst)[e4];
        int4 p = ((const int4*)g_pos)[e4];
        g_col[g_rowptr[d.x] + p.x] = s.x;
        g_col[g_rowptr[d.y] + p.y] = s.y;
        g_col[g_rowptr[d.z] + p.z] = s.z;
        g_col[g_rowptr[d.w] + p.w] = s.w;
    }
}

// ---------------- weight image precompute (both layers, one launch) ----------
__global__ void k_wimg2(const float* __restrict__ W1, const float* __restrict__ W2) {
    int gidx = blockIdx.x * blockDim.x + threadIdx.x;     // 0..16383
    int layer = gidx >> 13;                               // 0 or 1
    int idx = gidx & 8191;
    const float* W = (layer == 0 ? W1 : W2);
    uint32_t* img = (layer == 0 ? g_W1i : g_W2i);
    int n = idx >> 6, cp = idx & 63;
    int k0 = 2 * cp;
    float w0 = W[(size_t)k0 * HID + n];
    float w1 = W[(size_t)(k0 + 1) * HID + n];
    __half h0 = __float2half_rn(w0), h1 = __float2half_rn(w1);
    img[idx] = (uint32_t)__half_as_ushort(h0) | ((uint32_t)__half_as_ushort(h1) << 16);
}

// ---------------- single-pass fp16 GEMM, M-tile 64, 3 CTAs/SM ----------------
// h'[r][:] = rsqrt(cnt[r]+1) * (A[r][:] @ W), stored fp16.
#define ROWW 68
#define MAT_A (64 * ROWW)
#define MAT_W (128 * ROWW)
#define DSMEM_SZ ((MAT_A + MAT_W) * 4)     // 52224 bytes

__device__ __forceinline__ void mma_f16(float* d, uint32_t a0, uint32_t a1,
                                        uint32_t a2, uint32_t a3,
                                        uint32_t b0, uint32_t b1) {
    asm volatile(
        "mma.sync.aligned.m16n8k16.row.col.f32.f16.f16.f32 "
        "{%0,%1,%2,%3}, {%4,%5,%6,%7}, {%8,%9}, {%0,%1,%2,%3};\n"
        : "+f"(d[0]), "+f"(d[1]), "+f"(d[2]), "+f"(d[3])
        : "r"(a0), "r"(a1), "r"(a2), "r"(a3), "r"(b0), "r"(b1));
}

__device__ __forceinline__ void ldsm_x4(uint32_t& r0, uint32_t& r1, uint32_t& r2,
                                        uint32_t& r3, uint32_t addr) {
    asm volatile("ldmatrix.sync.aligned.m8n8.x4.shared.b16 {%0,%1,%2,%3}, [%4];"
                 : "=r"(r0), "=r"(r1), "=r"(r2), "=r"(r3) : "r"(addr));
}

__global__ void __launch_bounds__(256, 3) k_gemm(const float* Af32, int layer) {
    extern __shared__ uint32_t sm[];
    uint32_t* sA = sm;
    uint32_t* sW = sm + MAT_A;

    const uint32_t* wImg = (layer == 0 ? g_W1i : g_W2i);
    __half* outH = (layer == 0 ? g_bufH1 : g_bufH2);

    int tid = threadIdx.x;
    int wid = tid >> 5, lane = tid & 31;
    int blockRow = blockIdx.x * 64;

    // Stage W image (uint2-vectorized)
    {
        const uint2* w2 = (const uint2*)wImg;
        #pragma unroll
        for (int i = 0; i < 16; i++) {
            int idx = tid + i * 256;
            int row = idx >> 5, uc = idx & 31;
            uint2 v = w2[idx];
            sW[row * ROWW + 2 * uc]     = v.x;
            sW[row * ROWW + 2 * uc + 1] = v.y;
        }
    }
    // A tile: layer 0 fp32 emb via float4; layer 1 fp16 x via uint2
    if (Af32) {
        #pragma unroll
        for (int i = 0; i < 8; i++) {
            int idx = tid + i * 256;
            int row = idx >> 5, c4 = idx & 31;
            int gr = blockRow + row;
            float4 v = make_float4(0.f, 0.f, 0.f, 0.f);
            if (gr < NN) v = ((const float4*)(Af32 + (size_t)gr * HID))[c4];
            __half h0 = __float2half_rn(v.x), h1 = __float2half_rn(v.y);
            __half h2 = __float2half_rn(v.z), h3 = __float2half_rn(v.w);
            sA[row * ROWW + 2 * c4]     = (uint32_t)__half_as_ushort(h0) | ((uint32_t)__half_as_ushort(h1) << 16);
            sA[row * ROWW + 2 * c4 + 1] = (uint32_t)__half_as_ushort(h2) | ((uint32_t)__half_as_ushort(h3) << 16);
        }
    } else {
        #pragma unroll
        for (int i = 0; i < 8; i++) {
            int idx = tid + i * 256;
            int row = idx >> 5, uc = idx & 31;
            int gr = blockRow + row;
            uint2 v = make_uint2(0u, 0u);
            if (gr < NN) v = ((const uint2*)(g_bufX + (size_t)gr * HID))[uc];
            sA[row * ROWW + 2 * uc]     = v.x;
            sA[row * ROWW + 2 * uc + 1] = v.y;
        }
    }
    __syncthreads();

    float acc[8][4];
    #pragma unroll
    for (int j = 0; j < 8; j++)
        #pragma unroll
        for (int q = 0; q < 4; q++) acc[j][q] = 0.f;

    int rowGrp = wid & 3, nHalf = wid >> 2;
    int grp = lane >> 3, l8 = lane & 7;
    uint32_t base = smem_u32(sm);
    uint32_t aAddr = base + (uint32_t)((rowGrp * 16 + (grp & 1) * 8 + l8) * ROWW + (grp >> 1) * 4) * 4;
    uint32_t wAddr = base + MAT_A * 4 +
                     (uint32_t)((nHalf * 64 + (grp >> 1) * 8 + l8) * ROWW + (grp & 1) * 4) * 4;

    #pragma unroll
    for (int kc = 0; kc < 8; kc++) {
        uint32_t kB = kc * 32;
        uint32_t a0, a1, a2, a3;
        ldsm_x4(a0, a1, a2, a3, aAddr + kB);
        #pragma unroll
        for (int jp = 0; jp < 4; jp++) {
            uint32_t jB = (uint32_t)(jp * 16 * ROWW) * 4 + kB;
            uint32_t b0, b1, b2, b3;
            ldsm_x4(b0, b1, b2, b3, wAddr + jB);
            mma_f16(acc[2 * jp],     a0, a1, a2, a3, b0, b1);
            mma_f16(acc[2 * jp + 1], a0, a1, a2, a3, b2, b3);
        }
    }

    // Epilogue: scale by rsqrt(cnt+1), store fp16 h'
    int g = lane >> 2, t = lane & 3;
    int gr0 = blockRow + rowGrp * 16 + g;
    int gr1 = gr0 + 8;
    float wn0 = (gr0 < NN) ? rsqrtf((float)(g_cnt[gr0] + 1)) : 0.f;
    float wn1 = (gr1 < NN) ? rsqrtf((float)(g_cnt[gr1] + 1)) : 0.f;
    #pragma unroll
    for (int j = 0; j < 8; j++) {
        int col = nHalf * 64 + j * 8 + 2 * t;
        if (gr0 < NN)
            *(__half2*)&outH[(size_t)gr0 * HID + col] =
                __floats2half2_rn(wn0 * acc[j][0], wn0 * acc[j][1]);
        if (gr1 < NN)
            *(__half2*)&outH[(size_t)gr1 * HID + col] =
                __floats2half2_rn(wn1 * acc[j][2], wn1 * acc[j][3]);
    }
}

// ---------------- gather-aggregate + bias + relu (+ fused output proj) -------
// agg[n] = rsqrt(cnt[n]+1) * sum_{s in N(n) U {n}} h'[s];  x = relu(agg + b)
__global__ void k_agg(int layer, const float* __restrict__ bias,
                      const float* __restrict__ Wout, const float* __restrict__ bout,
                      float* __restrict__ out) {
    const __half* h = (layer == 0 ? g_bufH1 : g_bufH2);
    __shared__ float Ws[HID * NC];
    __shared__ float bs[NC];

    int tid = threadIdx.x;
    if (Wout) {
        for (int i = tid; i < HID * NC; i += blockDim.x) Ws[i] = Wout[i];
        if (tid < NC) bs[tid] = bout[tid];
        __syncthreads();
    }

    int n = (blockIdx.x * blockDim.x + tid) >> 5;     // grid exact: 100000 warps
    int lane = tid & 31;

    float ax, ay, az, aw;
    {
        uint2 v = ((const uint2*)(h + (size_t)n * HID))[lane];
        float2 p0 = __half22float2(*(const __half2*)&v.x);
        float2 p1 = __half22float2(*(const __half2*)&v.y);
        ax = p0.x; ay = p0.y; az = p1.x; aw = p1.y;   // self term h'[n]
    }

    int beg = g_rowptr[n];
    int cnt = g_cnt[n];
    int end = beg + cnt;

    int idx = beg;
    // 8-way unroll: 8 outstanding row-gathers per iteration
    for (; idx + 7 < end; idx += 8) {
        int s0 = g_col[idx],     s1 = g_col[idx + 1];
        int s2 = g_col[idx + 2], s3 = g_col[idx + 3];
        int s4 = g_col[idx + 4], s5 = g_col[idx + 5];
        int s6 = g_col[idx + 6], s7 = g_col[idx + 7];
        uint2 v0 = ((const uint2*)(h + (size_t)s0 * HID))[lane];
        uint2 v1 = ((const uint2*)(h + (size_t)s1 * HID))[lane];
        uint2 v2 = ((const uint2*)(h + (size_t)s2 * HID))[lane];
        uint2 v3 = ((const uint2*)(h + (size_t)s3 * HID))[lane];
        uint2 v4 = ((const uint2*)(h + (size_t)s4 * HID))[lane];
        uint2 v5 = ((const uint2*)(h + (size_t)s5 * HID))[lane];
        uint2 v6 = ((const uint2*)(h + (size_t)s6 * HID))[lane];
        uint2 v7 = ((const uint2*)(h + (size_t)s7 * HID))[lane];
        float2 a0 = __half22float2(*(const __half2*)&v0.x), b0 = __half22float2(*(const __half2*)&v0.y);
        float2 a1 = __half22float2(*(const __half2*)&v1.x), b1 = __half22float2(*(const __half2*)&v1.y);
        float2 a2 = __half22float2(*(const __half2*)&v2.x), b2 = __half22float2(*(const __half2*)&v2.y);
        float2 a3 = __half22float2(*(const __half2*)&v3.x), b3 = __half22float2(*(const __half2*)&v3.y);
        float2 a4 = __half22float2(*(const __half2*)&v4.x), b4 = __half22float2(*(const __half2*)&v4.y);
        float2 a5 = __half22float2(*(const __half2*)&v5.x), b5 = __half22float2(*(const __half2*)&v5.y);
        float2 a6 = __half22float2(*(const __half2*)&v6.x), b6 = __half22float2(*(const __half2*)&v6.y);
        float2 a7 = __half22float2(*(const __half2*)&v7.x), b7 = __half22float2(*(const __half2*)&v7.y);
        ax += ((a0.x + a1.x) + (a2.x + a3.x)) + ((a4.x + a5.x) + (a6.x + a7.x));
        ay += ((a0.y + a1.y) + (a2.y + a3.y)) + ((a4.y + a5.y) + (a6.y + a7.y));
        az += ((b0.x + b1.x) + (b2.x + b3.x)) + ((b4.x + b5.x) + (b6.x + b7.x));
        aw += ((b0.y + b1.y) + (b2.y + b3.y)) + ((b4.y + b5.y) + (b6.y + b7.y));
    }
    for (; idx + 3 < end; idx += 4) {
        int s0 = g_col[idx],     s1 = g_col[idx + 1];
        int s2 = g_col[idx + 2], s3 = g_col[idx + 3];
        uint2 v0 = ((const uint2*)(h + (size_t)s0 * HID))[lane];
        uint2 v1 = ((const uint2*)(h + (size_t)s1 * HID))[lane];
        uint2 v2 = ((const uint2*)(h + (size_t)s2 * HID))[lane];
        uint2 v3 = ((const uint2*)(h + (size_t)s3 * HID))[lane];
        float2 a0 = __half22float2(*(const __half2*)&v0.x), b0 = __half22float2(*(const __half2*)&v0.y);
        float2 a1 = __half22float2(*(const __half2*)&v1.x), b1 = __half22float2(*(const __half2*)&v1.y);
        float2 a2 = __half22float2(*(const __half2*)&v2.x), b2 = __half22float2(*(const __half2*)&v2.y);
        float2 a3 = __half22float2(*(const __half2*)&v3.x), b3 = __half22float2(*(const __half2*)&v3.y);
        ax += (a0.x + a1.x) + (a2.x + a3.x);
        ay += (a0.y + a1.y) + (a2.y + a3.y);
        az += (b0.x + b1.x) + (b2.x + b3.x);
        aw += (b0.y + b1.y) + (b2.y + b3.y);
    }
    for (; idx < end; idx++) {
        int s0 = g_col[idx];
        uint2 v0 = ((const uint2*)(h + (size_t)s0 * HID))[lane];
        float2 a0 = __half22float2(*(const __half2*)&v0.x);
        float2 b0 = __half22float2(*(const __half2*)&v0.y);
        ax += a0.x; ay += a0.y; az += b0.x; aw += b0.y;
    }

    float wn = rsqrtf((float)(cnt + 1));
    float4 bv = ((const float4*)bias)[lane];
    float4 r;
    r.x = fmaxf(wn * ax + bv.x, 0.f);
    r.y = fmaxf(wn * ay + bv.y, 0.f);
    r.z = fmaxf(wn * az + bv.z, 0.f);
    r.w = fmaxf(wn * aw + bv.w, 0.f);

    if (!Wout) {
        uint2 o;
        *(__half2*)&o.x = __floats2half2_rn(r.x, r.y);
        *(__half2*)&o.y = __floats2half2_rn(r.z, r.w);
        ((uint2*)(g_bufX + (size_t)n * HID))[lane] = o;
    } else {
        int kb = lane * 4;
        #pragma unroll
        for (int c = 0; c < NC; c++) {
            float s = r.x * Ws[(kb + 0) * NC + c]
                    + r.y * Ws[(kb + 1) * NC + c]
                    + r.z * Ws[(kb + 2) * NC + c]
                    + r.w * Ws[(kb + 3) * NC + c];
            #pragma unroll
            for (int off = 16; off; off >>= 1)
                s += __shfl_down_sync(0xffffffffu, s, off);
            if (lane == 0) out[(size_t)n * NC + c] = s + bs[c];
        }
    }
}

// ---------------- launch ----------------
extern "C" void kernel_launch(void* const* d_in, const int* in_sizes, int n_in,
                              void* d_out, int out_size) {
    const int*   src  = (const int*)d_in[0];          // edge_index[0]
    const int*   dst  = src + NE;                     // edge_index[1]
    const float* emb  = (const float*)d_in[1];
    const float* W1   = (const float*)d_in[2];
    const float* b1   = (const float*)d_in[3];
    const float* W2   = (const float*)d_in[4];
    const float* b2   = (const float*)d_in[5];
    const float* Wout = (const float*)d_in[6];
    const float* bout = (const float*)d_in[7];
    float* out = (float*)d_out;

    const int SCAN_BLKS  = (NN + 511) / 512;          // 196
    const int EDGE4_BLKS = (NE / 4 + 255) / 256;      // 1563
    const int GEMM_BLKS  = (NN + 63) / 64;            // 1563
    const int AGG_BLKS   = (NN * 32) / 256;           // 12500

    static cudaStream_t s2 = nullptr;
    static cudaEvent_t evF = nullptr, evI = nullptr, evJ = nullptr;
    static void* cntAddr = nullptr;
    if (!s2) {
        cudaFuncSetAttribute(k_gemm, cudaFuncAttributeMaxDynamicSharedMemorySize, DSMEM_SZ);
        cudaStreamCreateWithFlags(&s2, cudaStreamNonBlocking);
        cudaEventCreateWithFlags(&evF, cudaEventDisableTiming);
        cudaEventCreateWithFlags(&evI, cudaEventDisableTiming);
        cudaEventCreateWithFlags(&evJ, cudaEventDisableTiming);
        cudaGetSymbolAddress(&cntAddr, g_cnt);
    }

    // Fork: side stream builds both weight images in one launch
    cudaEventRecord(evF, 0);
    cudaStreamWaitEvent(s2, evF, 0);
    k_wimg2<<<64, 256, 0, s2>>>(W1, W2);

    // Main stream: counts (GEMM1's only prep dependency — epilogue rsqrt inline)
    cudaMemsetAsync(cntAddr, 0, NN * sizeof(int), 0);
    k_count<<<EDGE4_BLKS, 256>>>(dst);
    cudaEventRecord(evI, 0);

    // Side stream: GEMM1 overlaps remaining CSR build
    cudaStreamWaitEvent(s2, evI, 0);
    k_gemm<<<GEMM_BLKS, 256, DSMEM_SZ, s2>>>(emb, 0);
    cudaEventRecord(evJ, s2);

    // Main stream: rest of CSR build
    k_scanA<<<SCAN_BLKS, 512>>>();
    k_scanB<<<1, 256>>>(SCAN_BLKS);
    k_scanC<<<SCAN_BLKS, 512>>>();
    k_place<<<EDGE4_BLKS, 256>>>(src, dst);

    // Join, then layer-1 agg -> layer-2 GEMM -> layer-2 agg + output proj
    cudaStreamWaitEvent(0, evJ, 0);
    k_agg<<<AGG_BLKS, 256>>>(0, b1, nullptr, nullptr, nullptr);
    k_gemm<<<GEMM_BLKS, 256, DSMEM_SZ>>>(nullptr, 1);
    k_agg<<<AGG_BLKS, 256>>>(1, b2, Wout, bout, out);
}